// round 7
// baseline (speedup 1.0000x reference)
#include <cuda_runtime.h>
#include <cuda_bf16.h>
#include <math.h>

#define D        80
#define DP       88          // padded smem row stride (bf16): conflict-free frag loads
#define NMAX     8192
#define TILE     128         // M and N tile
#define NCHUNK   2           // grid = 64*2 = 128 blocks -> single wave on 148 SMs

#define TILE_BYTES (TILE * DP * 2)                  // 22528 B per smem tile
#define SMEM_DYN   (3 * TILE_BYTES)                 // sA + sB0 + sB1 = 67584 B

// bf16 normalized matrices, row-major [N][D]. g_A is pre-scaled by log2(e).
__device__ __align__(16) __nv_bfloat16 g_A[NMAX * D];
__device__ __align__(16) __nv_bfloat16 g_B[NMAX * D];
__device__ float g_pos[NMAX];                            // exact fp32 diagonal sims
__device__ float g_psum[(NMAX / TILE) * NCHUNK * TILE];

__device__ __forceinline__ float ex2f(float x) {
    float y;
    asm("ex2.approx.f32 %0, %1;" : "=f"(y) : "f"(x));
    return y;
}

// ---------------------------------------------------------------------------
// Kernel 1: fused L2-normalize (both matrices) + exact fp32 diagonal sim.
// Warp-per-row: block = 256 (8 rows), grid = N/8. No smem, no barriers.
// ---------------------------------------------------------------------------
__global__ void mmi_prep(const float* __restrict__ o,
                         const float* __restrict__ t, int N) {
    const int wid  = threadIdx.x >> 5;
    const int lane = threadIdx.x & 31;
    const int row  = blockIdx.x * 8 + wid;

    float xv[3], yv[3];
    float oo = 0.f, tt = 0.f, ot = 0.f;
#pragma unroll
    for (int j = 0; j < 3; j++) {
        const int k = lane + j * 32;
        const bool ok = (k < D);
        xv[j] = ok ? o[row * D + k] : 0.f;
        yv[j] = ok ? t[row * D + k] : 0.f;
        oo += xv[j] * xv[j];
        tt += yv[j] * yv[j];
        ot += xv[j] * yv[j];
    }
#pragma unroll
    for (int off = 16; off > 0; off >>= 1) {
        oo += __shfl_xor_sync(0xffffffffu, oo, off);
        tt += __shfl_xor_sync(0xffffffffu, tt, off);
        ot += __shfl_xor_sync(0xffffffffu, ot, off);
    }
    const float no = fmaxf(sqrtf(oo), 1e-12f);
    const float nt = fmaxf(sqrtf(tt), 1e-12f);
    const float sa = 1.4426950408889634f / no;   // log2(e)/||o||
    const float sb = 1.0f / nt;

#pragma unroll
    for (int j = 0; j < 3; j++) {
        const int k = lane + j * 32;
        if (k < D) {
            g_A[row * D + k] = __float2bfloat16(xv[j] * sa);
            g_B[row * D + k] = __float2bfloat16(yv[j] * sb);
        }
    }
    if (lane == 0) g_pos[row] = ot / (no * nt);
}

// ---------------------------------------------------------------------------
// mma.sync m16n8k16 bf16
// ---------------------------------------------------------------------------
__device__ __forceinline__ void mma16816(float c[4],
                                         const unsigned a[4],
                                         const unsigned b0, const unsigned b1) {
    asm volatile(
        "mma.sync.aligned.m16n8k16.row.col.f32.bf16.bf16.f32 "
        "{%0,%1,%2,%3}, {%4,%5,%6,%7}, {%8,%9}, {%0,%1,%2,%3};"
        : "+f"(c[0]), "+f"(c[1]), "+f"(c[2]), "+f"(c[3])
        : "r"(a[0]), "r"(a[1]), "r"(a[2]), "r"(a[3]), "r"(b0), "r"(b1));
}

// ---------------------------------------------------------------------------
// Kernel 2: fused bf16 sim-GEMM + exp2 row-sums. Double-buffered sB:
// per tile: MMA(read cur) -> exp -> STS(next) -> ONE BAR.
// grid = 128 (single wave), block = 256 (8 warps 2x4), warp tile 64x32.
// ---------------------------------------------------------------------------
__global__ void __launch_bounds__(256, 1)
mmi_main(int N) {
    extern __shared__ __align__(16) char dyn[];
    __nv_bfloat16* sA  = (__nv_bfloat16*)dyn;                    // 22528 B
    __nv_bfloat16* sB0 = (__nv_bfloat16*)(dyn + TILE_BYTES);     // 22528 B
    __nv_bfloat16* sB1 = (__nv_bfloat16*)(dyn + 2 * TILE_BYTES); // 22528 B
    __shared__ float sSums[TILE * 4];                            // [row][warpN]

    const int tid   = threadIdx.x;
    const int wid   = tid >> 5;
    const int lane  = tid & 31;
    const int l4    = lane >> 2;
    const int lm    = lane & 3;
    const int warpM = wid >> 2;
    const int warpN = wid & 3;
    const int wr    = warpM * 64;

    const int rt = blockIdx.x / NCHUNK;
    const int ch = blockIdx.x - rt * NCHUNK;
    const int rb = rt * TILE;
    const int tilesPerChunk = (N / TILE) / NCHUNK;   // 32
    const int colBeg = ch * tilesPerChunk * TILE;

    // per-thread STS slots (5 uint4 each, fixed across tiles)
    int srow[5], scol[5];
#pragma unroll
    for (int j = 0; j < 5; j++) {
        const int v = tid + j * 256;
        srow[j] = v / (D / 8);
        scol[j] = (v - srow[j] * (D / 8)) * 8;
    }

    // stage A tile (128 x 80 bf16) as uint4
#pragma unroll
    for (int j = 0; j < 5; j++)
        *(uint4*)&sA[srow[j] * DP + scol[j]] =
            *(const uint4*)&g_A[(rb + srow[j]) * D + scol[j]];

    // load + store B tile 0 into sB0
    uint4 pf[5];
#pragma unroll
    for (int j = 0; j < 5; j++)
        pf[j] = *(const uint4*)&g_B[(colBeg + srow[j]) * D + scol[j]];
#pragma unroll
    for (int j = 0; j < 5; j++)
        *(uint4*)&sB0[srow[j] * DP + scol[j]] = pf[j];
    __syncthreads();   // sA + sB0 visible

    // hoist all A fragments (5 k-chunks x 4 m-frags) — col-tile invariant
    unsigned afr[5][4][4];
#pragma unroll
    for (int kc = 0; kc < 5; kc++) {
#pragma unroll
        for (int i = 0; i < 4; i++) {
            const int r0 = wr + i * 16 + l4;
            const int k0 = kc * 16 + lm * 2;
            afr[kc][i][0] = *(const unsigned*)&sA[r0 * DP + k0];
            afr[kc][i][1] = *(const unsigned*)&sA[(r0 + 8) * DP + k0];
            afr[kc][i][2] = *(const unsigned*)&sA[r0 * DP + k0 + 8];
            afr[kc][i][3] = *(const unsigned*)&sA[(r0 + 8) * DP + k0 + 8];
        }
    }

    float rowsum[8];
#pragma unroll
    for (int p = 0; p < 8; p++) rowsum[p] = 0.f;

    for (int tt = 0; tt < tilesPerChunk; tt++) {
        const __nv_bfloat16* cur = (tt & 1) ? sB1 : sB0;
        __nv_bfloat16*       nxt = (tt & 1) ? sB0 : sB1;
        const bool more = (tt + 1 < tilesPerChunk);

        // issue next tile's loads first — latency hidden under the MMAs
        if (more) {
            const int nb = colBeg + (tt + 1) * TILE;
#pragma unroll
            for (int j = 0; j < 5; j++)
                pf[j] = *(const uint4*)&g_B[(nb + srow[j]) * D + scol[j]];
        }

        float c4[4][4][4];
#pragma unroll
        for (int i = 0; i < 4; i++)
#pragma unroll
            for (int j = 0; j < 4; j++)
#pragma unroll
                for (int q = 0; q < 4; q++) c4[i][j][q] = 0.f;

#pragma unroll
        for (int kc = 0; kc < 5; kc++) {
            unsigned b0[4], b1[4];
#pragma unroll
            for (int j = 0; j < 4; j++) {
                const int n0 = warpN * 32 + j * 8 + l4;
                const int k0 = kc * 16 + lm * 2;
                b0[j] = *(const unsigned*)&cur[n0 * DP + k0];
                b1[j] = *(const unsigned*)&cur[n0 * DP + k0 + 8];
            }
#pragma unroll
            for (int i = 0; i < 4; i++)
#pragma unroll
                for (int j = 0; j < 4; j++)
                    mma16816(c4[i][j], afr[kc][i], b0[j], b1[j]);
        }

        // c4 holds log2(e)*sim -> exp via raw EX2
#pragma unroll
        for (int i = 0; i < 4; i++) {
            float s01 = 0.f, s23 = 0.f;
#pragma unroll
            for (int j = 0; j < 4; j++) {
                s01 += ex2f(c4[i][j][0]) + ex2f(c4[i][j][1]);
                s23 += ex2f(c4[i][j][2]) + ex2f(c4[i][j][3]);
            }
            rowsum[2 * i]     += s01;   // row wr + i*16 + l4
            rowsum[2 * i + 1] += s23;   // row wr + i*16 + l4 + 8
        }

        // store next tile into the other buffer; single barrier per tile
        if (more) {
#pragma unroll
            for (int j = 0; j < 5; j++)
                *(uint4*)&nxt[srow[j] * DP + scol[j]] = pf[j];
        }
        __syncthreads();
    }

    // reduce over lm (disjoint column pairs of same rows)
#pragma unroll
    for (int p = 0; p < 8; p++) {
        rowsum[p] += __shfl_xor_sync(0xffffffffu, rowsum[p], 1);
        rowsum[p] += __shfl_xor_sync(0xffffffffu, rowsum[p], 2);
    }
    if (lm == 0) {
#pragma unroll
        for (int p = 0; p < 8; p++) {
            const int r = wr + (p >> 1) * 16 + l4 + (p & 1) * 8;
            sSums[r * 4 + warpN] = rowsum[p];
        }
    }
    __syncthreads();

    if (tid < TILE) {
        const float tot = sSums[tid * 4 + 0] + sSums[tid * 4 + 1] +
                          sSums[tid * 4 + 2] + sSums[tid * 4 + 3];
        g_psum[blockIdx.x * TILE + tid] = tot;
    }
}

// ---------------------------------------------------------------------------
// Kernel 3: loss = mean( log(sum_chunks) - pos ). 1 block x 512 threads.
// ---------------------------------------------------------------------------
__global__ void mmi_finalize(float* __restrict__ out, int N) {
    __shared__ float s[512];
    const int tid = threadIdx.x;
    float acc = 0.f;
    for (int r = tid; r < N; r += 512) {
        const int rt = r / TILE;
        const int ri = r - rt * TILE;
        float tot = 0.f;
#pragma unroll
        for (int c = 0; c < NCHUNK; c++)
            tot += g_psum[(rt * NCHUNK + c) * TILE + ri];
        acc += logf(tot) - g_pos[r];
    }
    s[tid] = acc;
    __syncthreads();
#pragma unroll
    for (int off = 256; off > 0; off >>= 1) {
        if (tid < off) s[tid] += s[tid + off];
        __syncthreads();
    }
    if (tid == 0) out[0] = s[0] / (float)N;
}

// ---------------------------------------------------------------------------
extern "C" void kernel_launch(void* const* d_in, const int* in_sizes, int n_in,
                              void* d_out, int out_size) {
    const float* o = (const float*)d_in[0];   // mel_outputs [B,T,D]
    const float* t = (const float*)d_in[1];   // mel_targets [B,T,D]
    float* out = (float*)d_out;

    const int N = in_sizes[0] / D;            // 8192

    static bool attr_set = false;             // host-side only; not device state
    if (!attr_set) {
        cudaFuncSetAttribute(mmi_main,
                             cudaFuncAttributeMaxDynamicSharedMemorySize,
                             SMEM_DYN);
        attr_set = true;
    }

    mmi_prep<<<N / 8, 256>>>(o, t, N);
    mmi_main<<<(N / TILE) * NCHUNK, 256, SMEM_DYN>>>(N);
    mmi_finalize<<<1, 512>>>(out, N);
}